// round 8
// baseline (speedup 1.0000x reference)
#include <cuda_runtime.h>

// out[b] = sum_j exp(-K2_j) * K2_j / sum_j exp(-K2_j),
// K2_j = (x_j - mean(x))^2 over all_atom_features of batch b.
// (softmax_j over -(Q2_i + K2_j) cancels Q2_i exactly -> cdr3 input unused.
//  K2 >= 0 so exp(-K2) <= 1: no max-shift needed for fp32 safety.)
//
// Latency/overhead-bound regime (grid=4, all pipes <0.5%): minimize block
// ramp/drain -> 4 warps/block (one per SMSP), 64 elems/thread in registers,
// 16 front-batched LDG.128 (high MLP), 2 barriers total.

#define M 8192
#define NTHREADS 128
#define NWARPS (NTHREADS / 32)   // 4
#define VECS  16                 // float4 loads per thread (64 elems)

__global__ __launch_bounds__(NTHREADS)
void invariant_cross_attention_kernel(const float4* __restrict__ atom4,
                                      float* __restrict__ out) {
    __shared__ float  red1[NWARPS];
    __shared__ float2 red2[NWARPS];

    const int tid  = threadIdx.x;
    const int lane = tid & 31;
    const int wid  = tid >> 5;
    const float4* __restrict__ x4 = atom4 + (size_t)blockIdx.x * (M / 4);

    // ---- Front-batched loads: 16x LDG.128 in flight ----
    float4 v[VECS];
    #pragma unroll
    for (int k = 0; k < VECS; k++) v[k] = x4[tid + k * NTHREADS];

    // ---- Reduction 1: sum -> mean (pairwise tree inside thread) ----
    float sum = 0.0f;
    {
        float p0 = 0.0f, p1 = 0.0f;
        #pragma unroll
        for (int k = 0; k < VECS; k += 2) {
            p0 += ((v[k].x + v[k].y) + (v[k].z + v[k].w));
            p1 += ((v[k+1].x + v[k+1].y) + (v[k+1].z + v[k+1].w));
        }
        sum = p0 + p1;
    }
    #pragma unroll
    for (int o = 16; o > 0; o >>= 1) sum += __shfl_down_sync(0xffffffffu, sum, o);
    if (lane == 0) red1[wid] = sum;
    __syncthreads();
    float total;
    {
        // redundant per-warp reduce of the 4 partials (no 2nd barrier/broadcast)
        float t = (lane < NWARPS) ? red1[lane] : 0.0f;
        t += __shfl_down_sync(0xffffffffu, t, 2);
        t += __shfl_down_sync(0xffffffffu, t, 1);
        total = __shfl_sync(0xffffffffu, t, 0);
    }
    const float mean = total * (1.0f / (float)M);

    // ---- Pass 2 (registers only): s = sum exp(-k2), num = sum exp(-k2)*k2 ----
    // Dual accumulators to shorten FFMA dependency chains behind MUFU results.
    float s0 = 0.0f, s1 = 0.0f, n0 = 0.0f, n1 = 0.0f;
    #pragma unroll
    for (int k = 0; k < VECS; k++) {
        float d0 = v[k].x - mean, d1 = v[k].y - mean,
              d2 = v[k].z - mean, d3 = v[k].w - mean;
        float a = d0 * d0, b = d1 * d1, c = d2 * d2, dd = d3 * d3;
        float e0 = __expf(-a), e1 = __expf(-b), e2 = __expf(-c), e3 = __expf(-dd);
        s0 += (e0 + e1);
        s1 += (e2 + e3);
        n0 = fmaf(e0, a, n0); n1 = fmaf(e1, b, n1);
        n0 = fmaf(e2, c, n0); n1 = fmaf(e3, dd, n1);
    }
    float s = s0 + s1, num = n0 + n1;

    // ---- Reduction 2: joint (s, num) ----
    #pragma unroll
    for (int o = 16; o > 0; o >>= 1) {
        s   += __shfl_down_sync(0xffffffffu, s, o);
        num += __shfl_down_sync(0xffffffffu, num, o);
    }
    if (lane == 0) red2[wid] = make_float2(s, num);
    __syncthreads();
    if (wid == 0 && lane < NWARPS) {
        float2 t = red2[lane];
        t.x += __shfl_down_sync(0xffffffffu, t.x, 2);
        t.y += __shfl_down_sync(0xffffffffu, t.y, 2);
        t.x += __shfl_down_sync(0xffffffffu, t.x, 1);
        t.y += __shfl_down_sync(0xffffffffu, t.y, 1);
        if (lane == 0) out[blockIdx.x] = t.y / t.x;
    }
}

extern "C" void kernel_launch(void* const* d_in, const int* in_sizes, int n_in,
                              void* d_out, int out_size) {
    // d_in[0] = cdr3_features  [4, 2048, 1] (mathematically irrelevant; unused)
    // d_in[1] = all_atom_features [4, 8192, 1]
    const float4* atom4 = (const float4*)d_in[1];
    float* out = (float*)d_out;
    const int B = in_sizes[1] / M;   // 4
    invariant_cross_attention_kernel<<<B, NTHREADS>>>(atom4, out);
}

// round 10
// speedup vs baseline: 1.1298x; 1.1298x over previous
#include <cuda_runtime.h>

// out[b] = sum_j exp(-K2_j) * K2_j / sum_j exp(-K2_j),
// K2_j = (x_j - mean(x))^2 over all_atom_features of batch b.
// (softmax_j over -(Q2_i + K2_j) cancels Q2_i exactly -> cdr3 input unused.
//  K2 >= 0 so exp(-K2) <= 1: no max-shift needed for fp32 safety.)
//
// Latency/overhead-bound regime (grid=4, all pipes <0.5%). Empirical best
// config: 8 warps/block, 32 elems/thread in registers, MLP=8 loads, 2 barriers.
// (1024 thr: 6.2us ncu; 128 thr: 5.0us + longer chains; 256 thr: 4.96us best.)

#define M 8192
#define NTHREADS 256
#define NWARPS (NTHREADS / 32)   // 8
#define VECS  8                  // float4 loads per thread (32 elems)

__global__ __launch_bounds__(NTHREADS)
void invariant_cross_attention_kernel(const float4* __restrict__ atom4,
                                      float* __restrict__ out) {
    __shared__ float  red1[NWARPS];
    __shared__ float2 red2[NWARPS];

    const int tid  = threadIdx.x;
    const int lane = tid & 31;
    const int wid  = tid >> 5;
    const float4* __restrict__ x4 = atom4 + (size_t)blockIdx.x * (M / 4);

    // ---- Front-batched loads: 8x LDG.128 in flight (MLP=8) ----
    float4 v[VECS];
    #pragma unroll
    for (int k = 0; k < VECS; k++) v[k] = x4[tid + k * NTHREADS];

    // ---- Reduction 1: sum -> mean (pairwise tree inside thread) ----
    float sum;
    {
        float p0 = 0.0f, p1 = 0.0f;
        #pragma unroll
        for (int k = 0; k < VECS; k += 2) {
            p0 += ((v[k].x + v[k].y) + (v[k].z + v[k].w));
            p1 += ((v[k+1].x + v[k+1].y) + (v[k+1].z + v[k+1].w));
        }
        sum = p0 + p1;
    }
    #pragma unroll
    for (int o = 16; o > 0; o >>= 1) sum += __shfl_down_sync(0xffffffffu, sum, o);
    if (lane == 0) red1[wid] = sum;
    __syncthreads();
    float total;
    {
        // redundant per-warp reduce of the 8 partials (no 2nd barrier/broadcast)
        float t = (lane < NWARPS) ? red1[lane] : 0.0f;
        t += __shfl_down_sync(0xffffffffu, t, 4);
        t += __shfl_down_sync(0xffffffffu, t, 2);
        t += __shfl_down_sync(0xffffffffu, t, 1);
        total = __shfl_sync(0xffffffffu, t, 0);
    }
    const float mean = total * (1.0f / (float)M);

    // ---- Pass 2 (registers only): s = sum exp(-k2), num = sum exp(-k2)*k2 ----
    // Dual accumulators to shorten FFMA dependency chains behind MUFU results.
    float s0 = 0.0f, s1 = 0.0f, n0 = 0.0f, n1 = 0.0f;
    #pragma unroll
    for (int k = 0; k < VECS; k++) {
        float d0 = v[k].x - mean, d1 = v[k].y - mean,
              d2 = v[k].z - mean, d3 = v[k].w - mean;
        float a = d0 * d0, b = d1 * d1, c = d2 * d2, dd = d3 * d3;
        float e0 = __expf(-a), e1 = __expf(-b), e2 = __expf(-c), e3 = __expf(-dd);
        s0 += (e0 + e1);
        s1 += (e2 + e3);
        n0 = fmaf(e0, a, n0); n1 = fmaf(e1, b, n1);
        n0 = fmaf(e2, c, n0); n1 = fmaf(e3, dd, n1);
    }
    float s = s0 + s1, num = n0 + n1;

    // ---- Reduction 2: joint (s, num) ----
    #pragma unroll
    for (int o = 16; o > 0; o >>= 1) {
        s   += __shfl_down_sync(0xffffffffu, s, o);
        num += __shfl_down_sync(0xffffffffu, num, o);
    }
    if (lane == 0) red2[wid] = make_float2(s, num);
    __syncthreads();
    if (wid == 0 && lane < NWARPS) {
        float2 t = red2[lane];
        t.x += __shfl_down_sync(0xffffffffu, t.x, 4);
        t.y += __shfl_down_sync(0xffffffffu, t.y, 4);
        t.x += __shfl_down_sync(0xffffffffu, t.x, 2);
        t.y += __shfl_down_sync(0xffffffffu, t.y, 2);
        t.x += __shfl_down_sync(0xffffffffu, t.x, 1);
        t.y += __shfl_down_sync(0xffffffffu, t.y, 1);
        if (lane == 0) out[blockIdx.x] = t.y / t.x;
    }
}

extern "C" void kernel_launch(void* const* d_in, const int* in_sizes, int n_in,
                              void* d_out, int out_size) {
    // d_in[0] = cdr3_features  [4, 2048, 1] (mathematically irrelevant; unused)
    // d_in[1] = all_atom_features [4, 8192, 1]
    const float4* atom4 = (const float4*)d_in[1];
    float* out = (float*)d_out;
    const int B = in_sizes[1] / M;   // 4
    invariant_cross_attention_kernel<<<B, NTHREADS>>>(atom4, out);
}